// round 11
// baseline (speedup 1.0000x reference)
#include <cuda_runtime.h>
#include <cuda_bf16.h>
#include <math.h>

// ---------------- Model constants ----------------
#define DEPTH   24
#define DM      192       // d_model
#define DI      384       // d_inner
#define DSTATE  16
#define DTRANK  12
#define DCONV   4
#define LSEQ    401       // NP+1
#define NB      4         // batch
#define MTOK    (NB*LSEQ) // 1604
#define DXP     (DTRANK + 2*DSTATE) // 44
#define CT      24        // scan chunk length

// ---------------- Scratch (device globals; no allocation) ----------------
__device__ float g_hidden  [MTOK*DM];
__device__ float g_residual[MTOK*DM];
__device__ float g_hnorm   [MTOK*DM];
__device__ float g_xz      [MTOK*2*DI];       // [:,0:384]=xx, [:,384:768]=z
__device__ float g_xconv   [2*MTOK*DI];       // per dir, silu(conv(x))
__device__ float g_dbl     [2*MTOK*DXP];      // xproj out [dt_r(12), B(16), C(16)]
__device__ float g_y       [2*MTOK*DI];       // gated outputs per dir

// ---------------- Patch embed + cls + pos ----------------
__global__ void k_patch(const float* __restrict__ x, const float* __restrict__ pe_w,
                        const float* __restrict__ pe_b, const float* __restrict__ cls,
                        const float* __restrict__ pos)
{
    int p = blockIdx.x;          // 0..399
    int b = blockIdx.y;          // 0..3
    int tid = threadIdx.x;       // 256
    __shared__ float sp[256];
    int ph = p / 200, pw = p % 200;
    int i = tid >> 4, j = tid & 15;
    sp[tid] = x[b*32*3200 + (ph*16 + i)*3200 + pw*16 + j];
    __syncthreads();
    if (tid < DM) {
        int c = tid;
        const float* w = pe_w + c*256;
        float acc = pe_b[c];
        #pragma unroll 8
        for (int k = 0; k < 256; k++) acc += sp[k]*w[k];
        int t = p + 1;
        float v = acc + pos[t*DM + c];
        int m = b*LSEQ + t;
        g_hidden[m*DM + c] = v;
        g_residual[m*DM + c] = v;
        if (p == 0) {
            float cv = cls[c] + pos[c];
            int m0 = b*LSEQ;
            g_hidden[m0*DM + c] = cv;
            g_residual[m0*DM + c] = cv;
        }
    }
}

// ---------------- residual += hidden ; hnorm = rmsnorm(residual)*w ----------------
__global__ void k_prenorm(const float* __restrict__ norm_w)
{
    int warp = threadIdx.x >> 5, lane = threadIdx.x & 31;
    int m = blockIdx.x*8 + warp;
    if (m >= MTOK) return;
    float r[6]; float ss = 0.f;
    #pragma unroll
    for (int u = 0; u < 6; u++) {
        int c = lane + u*32;
        float v = g_residual[m*DM + c] + g_hidden[m*DM + c];
        r[u] = v; ss += v*v;
        g_residual[m*DM + c] = v;
    }
    #pragma unroll
    for (int o = 16; o; o >>= 1) ss += __shfl_xor_sync(~0u, ss, o);
    float rstd = rsqrtf(ss*(1.f/DM) + 1e-5f);
    #pragma unroll
    for (int u = 0; u < 6; u++) {
        int c = lane + u*32;
        g_hnorm[m*DM + c] = r[u]*rstd*norm_w[c];
    }
}

// ---------------- GEMM0: g_xz[1604,768] = g_hnorm[1604,192] @ W[768,192]^T ----------------
// 128x64 tile, 256 thr, 8x4 acc, KT=16, double-buffered
__global__ void k_gemm0(const float* __restrict__ W)
{
    __shared__ float As[2][16][132];
    __shared__ float Ws[2][16][68];
    int tid = threadIdx.x;
    int m0 = blockIdx.x*128, n0 = blockIdx.y*64;
    int arow = tid >> 1, akq = (tid & 1)*2;
    int wrow = tid >> 2, wkq = tid & 3;
    int tx = tid & 15, ty = tid >> 4;
    float4 pa0, pa1, pw;

    {
        int m = m0 + arow;
        if (m < MTOK) {
            pa0 = *(const float4*)(g_hnorm + m*DM + akq*4);
            pa1 = *(const float4*)(g_hnorm + m*DM + akq*4 + 4);
        } else { pa0 = make_float4(0,0,0,0); pa1 = pa0; }
        pw = *(const float4*)(W + (n0 + wrow)*DM + wkq*4);
        As[0][akq*4+0][arow]=pa0.x; As[0][akq*4+1][arow]=pa0.y;
        As[0][akq*4+2][arow]=pa0.z; As[0][akq*4+3][arow]=pa0.w;
        As[0][akq*4+4][arow]=pa1.x; As[0][akq*4+5][arow]=pa1.y;
        As[0][akq*4+6][arow]=pa1.z; As[0][akq*4+7][arow]=pa1.w;
        Ws[0][wkq*4+0][wrow]=pw.x;  Ws[0][wkq*4+1][wrow]=pw.y;
        Ws[0][wkq*4+2][wrow]=pw.z;  Ws[0][wkq*4+3][wrow]=pw.w;
    }
    __syncthreads();

    float acc[8][4] = {};
    const int NK = DM/16;  // 12
    for (int kt = 0; kt < NK; kt++) {
        if (kt + 1 < NK) {
            int k0 = (kt+1)*16;
            int m = m0 + arow;
            if (m < MTOK) {
                pa0 = *(const float4*)(g_hnorm + m*DM + k0 + akq*4);
                pa1 = *(const float4*)(g_hnorm + m*DM + k0 + akq*4 + 4);
            } else { pa0 = make_float4(0,0,0,0); pa1 = pa0; }
            pw = *(const float4*)(W + (n0 + wrow)*DM + k0 + wkq*4);
        }
        int buf = kt & 1;
        #pragma unroll
        for (int k = 0; k < 16; k++) {
            float4 bv = *(const float4*)&Ws[buf][k][tx*4];
            float4 a0 = *(const float4*)&As[buf][k][ty*8];
            float4 a1 = *(const float4*)&As[buf][k][ty*8+4];
            float av[8] = {a0.x,a0.y,a0.z,a0.w,a1.x,a1.y,a1.z,a1.w};
            float bw[4] = {bv.x,bv.y,bv.z,bv.w};
            #pragma unroll
            for (int i2 = 0; i2 < 8; i2++)
                #pragma unroll
                for (int j2 = 0; j2 < 4; j2++)
                    acc[i2][j2] = fmaf(av[i2], bw[j2], acc[i2][j2]);
        }
        if (kt + 1 < NK) {
            int bn = buf ^ 1;
            As[bn][akq*4+0][arow]=pa0.x; As[bn][akq*4+1][arow]=pa0.y;
            As[bn][akq*4+2][arow]=pa0.z; As[bn][akq*4+3][arow]=pa0.w;
            As[bn][akq*4+4][arow]=pa1.x; As[bn][akq*4+5][arow]=pa1.y;
            As[bn][akq*4+6][arow]=pa1.z; As[bn][akq*4+7][arow]=pa1.w;
            Ws[bn][wkq*4+0][wrow]=pw.x;  Ws[bn][wkq*4+1][wrow]=pw.y;
            Ws[bn][wkq*4+2][wrow]=pw.z;  Ws[bn][wkq*4+3][wrow]=pw.w;
        }
        __syncthreads();
    }
    #pragma unroll
    for (int i2 = 0; i2 < 8; i2++) {
        int m = m0 + ty*8 + i2;
        if (m < MTOK) {
            float4 v = make_float4(acc[i2][0], acc[i2][1], acc[i2][2], acc[i2][3]);
            *(float4*)(g_xz + m*2*DI + n0 + tx*4) = v;
        }
    }
}

// ---------------- GEMM1: g_hidden[1604,192] = (y0+y1)[1604,384] @ W[192,384]^T ----------------
__global__ void k_gemm1(const float* __restrict__ W)
{
    __shared__ float As[2][32][68];
    __shared__ float Ws[2][32][68];
    int tid = threadIdx.x;
    int m0 = blockIdx.x*64, n0 = blockIdx.y*64;
    int row = tid >> 2, kq0 = (tid & 3)*2;
    int tx = tid & 15, ty = tid >> 4;
    float4 pa0, pa1, pw0, pw1;

    {
        int m = m0 + row;
        if (m < MTOK) {
            float4 a = *(const float4*)(g_y + m*DI + kq0*4);
            float4 b = *(const float4*)(g_y + (size_t)MTOK*DI + m*DI + kq0*4);
            pa0 = make_float4(a.x+b.x, a.y+b.y, a.z+b.z, a.w+b.w);
            a = *(const float4*)(g_y + m*DI + kq0*4 + 4);
            b = *(const float4*)(g_y + (size_t)MTOK*DI + m*DI + kq0*4 + 4);
            pa1 = make_float4(a.x+b.x, a.y+b.y, a.z+b.z, a.w+b.w);
        } else { pa0 = make_float4(0,0,0,0); pa1 = pa0; }
        pw0 = *(const float4*)(W + (n0 + row)*DI + kq0*4);
        pw1 = *(const float4*)(W + (n0 + row)*DI + kq0*4 + 4);
        As[0][kq0*4+0][row]=pa0.x; As[0][kq0*4+1][row]=pa0.y;
        As[0][kq0*4+2][row]=pa0.z; As[0][kq0*4+3][row]=pa0.w;
        As[0][kq0*4+4][row]=pa1.x; As[0][kq0*4+5][row]=pa1.y;
        As[0][kq0*4+6][row]=pa1.z; As[0][kq0*4+7][row]=pa1.w;
        Ws[0][kq0*4+0][row]=pw0.x; Ws[0][kq0*4+1][row]=pw0.y;
        Ws[0][kq0*4+2][row]=pw0.z; Ws[0][kq0*4+3][row]=pw0.w;
        Ws[0][kq0*4+4][row]=pw1.x; Ws[0][kq0*4+5][row]=pw1.y;
        Ws[0][kq0*4+6][row]=pw1.z; Ws[0][kq0*4+7][row]=pw1.w;
    }
    __syncthreads();

    float acc[4][4] = {};
    const int NK = DI/32;  // 12
    for (int kt = 0; kt < NK; kt++) {
        if (kt + 1 < NK) {
            int k0 = (kt+1)*32;
            int m = m0 + row;
            if (m < MTOK) {
                float4 a = *(const float4*)(g_y + m*DI + k0 + kq0*4);
                float4 b = *(const float4*)(g_y + (size_t)MTOK*DI + m*DI + k0 + kq0*4);
                pa0 = make_float4(a.x+b.x, a.y+b.y, a.z+b.z, a.w+b.w);
                a = *(const float4*)(g_y + m*DI + k0 + kq0*4 + 4);
                b = *(const float4*)(g_y + (size_t)MTOK*DI + m*DI + k0 + kq0*4 + 4);
                pa1 = make_float4(a.x+b.x, a.y+b.y, a.z+b.z, a.w+b.w);
            } else { pa0 = make_float4(0,0,0,0); pa1 = pa0; }
            pw0 = *(const float4*)(W + (n0 + row)*DI + k0 + kq0*4);
            pw1 = *(const float4*)(W + (n0 + row)*DI + k0 + kq0*4 + 4);
        }
        int buf = kt & 1;
        #pragma unroll
        for (int k = 0; k < 32; k++) {
            float4 bv = *(const float4*)&Ws[buf][k][tx*4];
            float4 a0 = *(const float4*)&As[buf][k][ty*4];
            float av[4] = {a0.x,a0.y,a0.z,a0.w};
            float bw[4] = {bv.x,bv.y,bv.z,bv.w};
            #pragma unroll
            for (int i2 = 0; i2 < 4; i2++)
                #pragma unroll
                for (int j2 = 0; j2 < 4; j2++)
                    acc[i2][j2] = fmaf(av[i2], bw[j2], acc[i2][j2]);
        }
        if (kt + 1 < NK) {
            int bn = buf ^ 1;
            As[bn][kq0*4+0][row]=pa0.x; As[bn][kq0*4+1][row]=pa0.y;
            As[bn][kq0*4+2][row]=pa0.z; As[bn][kq0*4+3][row]=pa0.w;
            As[bn][kq0*4+4][row]=pa1.x; As[bn][kq0*4+5][row]=pa1.y;
            As[bn][kq0*4+6][row]=pa1.z; As[bn][kq0*4+7][row]=pa1.w;
            Ws[bn][kq0*4+0][row]=pw0.x; Ws[bn][kq0*4+1][row]=pw0.y;
            Ws[bn][kq0*4+2][row]=pw0.z; Ws[bn][kq0*4+3][row]=pw0.w;
            Ws[bn][kq0*4+4][row]=pw1.x; Ws[bn][kq0*4+5][row]=pw1.y;
            Ws[bn][kq0*4+6][row]=pw1.z; Ws[bn][kq0*4+7][row]=pw1.w;
        }
        __syncthreads();
    }
    #pragma unroll
    for (int i2 = 0; i2 < 4; i2++) {
        int m = m0 + ty*4 + i2;
        if (m < MTOK) {
            float4 v = make_float4(acc[i2][0], acc[i2][1], acc[i2][2], acc[i2][3]);
            *(float4*)(g_hidden + m*DM + n0 + tx*4) = v;
        }
    }
}

// ---------------- GEMM2 with fused conv+silu A-path ----------------
// A[m,k] = silu(causal_dwconv(g_xz))[m,k] computed on the fly (also written to g_xconv)
// C = g_dbl[3208,44] = A @ W[44,384]^T ; 32-row tiles, grid 101, 192 thr
__global__ void k_gemm2conv(const float* __restrict__ W, const float* __restrict__ cw,
                            const float* __restrict__ cb)
{
    __shared__ float As[32][34];   // [k][m]
    __shared__ float Ws[32][52];   // [k][n]
    int tid = threadIdx.x;         // 192
    int m0 = blockIdx.x*32;
    int ty = tid / 12, tx = tid % 12;
    float acc[2][4] = {};
    for (int k0 = 0; k0 < DI; k0 += 32) {
        for (int i = tid; i < 256; i += 192) {
            int mr = i >> 3, kq = i & 7;
            int m = m0 + mr;
            float4 v = make_float4(0,0,0,0);
            if (m < 2*MTOK) {
                int dirm = (m >= MTOK) ? 1 : 0;
                int rr = m - dirm*MTOK;
                int bb = rr / LSEQ, t = rr - bb*LSEQ;
                int rb = bb*LSEQ;
                int k = k0 + kq*4;
                float4 cbv = *(const float4*)(cb + k);
                float4 cw0 = *(const float4*)(cw + (k+0)*4);
                float4 cw1 = *(const float4*)(cw + (k+1)*4);
                float4 cw2 = *(const float4*)(cw + (k+2)*4);
                float4 cw3 = *(const float4*)(cw + (k+3)*4);
                float c0[4] = {cw0.x, cw0.y, cw0.z, cw0.w};
                float c1[4] = {cw1.x, cw1.y, cw1.z, cw1.w};
                float c2[4] = {cw2.x, cw2.y, cw2.z, cw2.w};
                float c3[4] = {cw3.x, cw3.y, cw3.z, cw3.w};
                float a0 = cbv.x, a1 = cbv.y, a2 = cbv.z, a3 = cbv.w;
                #pragma unroll
                for (int tp = 0; tp < 4; tp++) {
                    int tt = dirm ? (t + 3 - tp) : (t - 3 + tp);
                    if (tt >= 0 && tt < LSEQ) {
                        float4 xv = *(const float4*)(g_xz + (size_t)(rb + tt)*2*DI + k);
                        a0 = fmaf(xv.x, c0[tp], a0);
                        a1 = fmaf(xv.y, c1[tp], a1);
                        a2 = fmaf(xv.z, c2[tp], a2);
                        a3 = fmaf(xv.w, c3[tp], a3);
                    }
                }
                v.x = a0 / (1.f + __expf(-a0));
                v.y = a1 / (1.f + __expf(-a1));
                v.z = a2 / (1.f + __expf(-a2));
                v.w = a3 / (1.f + __expf(-a3));
                *(float4*)(g_xconv + (size_t)m*DI + k) = v;
            }
            As[kq*4+0][mr]=v.x; As[kq*4+1][mr]=v.y; As[kq*4+2][mr]=v.z; As[kq*4+3][mr]=v.w;
        }
        for (int i = tid; i < 384; i += 192) {
            int nr = i >> 3, kq = i & 7;
            float4 v = make_float4(0,0,0,0);
            if (nr < DXP) v = *(const float4*)(W + nr*DI + k0 + kq*4);
            Ws[kq*4+0][nr]=v.x; Ws[kq*4+1][nr]=v.y; Ws[kq*4+2][nr]=v.z; Ws[kq*4+3][nr]=v.w;
        }
        __syncthreads();
        #pragma unroll
        for (int k = 0; k < 32; k++) {
            float2 a = *(const float2*)&As[k][ty*2];
            float4 w4 = *(const float4*)&Ws[k][tx*4];
            acc[0][0]=fmaf(a.x,w4.x,acc[0][0]); acc[0][1]=fmaf(a.x,w4.y,acc[0][1]);
            acc[0][2]=fmaf(a.x,w4.z,acc[0][2]); acc[0][3]=fmaf(a.x,w4.w,acc[0][3]);
            acc[1][0]=fmaf(a.y,w4.x,acc[1][0]); acc[1][1]=fmaf(a.y,w4.y,acc[1][1]);
            acc[1][2]=fmaf(a.y,w4.z,acc[1][2]); acc[1][3]=fmaf(a.y,w4.w,acc[1][3]);
        }
        __syncthreads();
    }
    if (tx < 11) {
        #pragma unroll
        for (int i2 = 0; i2 < 2; i2++) {
            int m = m0 + ty*2 + i2;
            if (m < 2*MTOK) {
                float4 v = make_float4(acc[i2][0], acc[i2][1], acc[i2][2], acc[i2][3]);
                *(float4*)(g_dbl + (size_t)m*DXP + tx*4) = v;
            }
        }
    }
}

// ---------------- selective scan with inline dt projection ----------------
__global__ void k_scan(const float* __restrict__ Alog_f, const float* __restrict__ Alog_b,
                       const float* __restrict__ Dp, const float* __restrict__ dtw,
                       const float* __restrict__ dtb)
{
    int cblk = blockIdx.x;  // 0..23
    int b = blockIdx.y;
    int dir = blockIdx.z;
    int tid = threadIdx.x;  // 256
    int warp = tid >> 5, lane = tid & 31;
    int dloc = warp*2 + (lane >> 4);
    int n = lane & 15;
    int d = cblk*16 + dloc;

    __shared__ float sbuf[2][5][CT*16];   // 0=dt 1=xv 2=B 3=C 4=z
    __shared__ float sp[CT][16][20];
    __shared__ float s_Dk[16];
    __shared__ float s_dtw[16][12];
    __shared__ float s_dtb[16];
    if (tid < 16) s_Dk[tid] = Dp[cblk*16 + tid];
    if (tid < 192) s_dtw[tid/12][tid%12] = dtw[(cblk*16 + tid/12)*DTRANK + (tid%12)];
    if (tid >= 192 && tid < 208) s_dtb[tid-192] = dtb[cblk*16 + tid - 192];

    const float* Alog = dir ? Alog_b : Alog_f;
    float A = -__expf(Alog[d*DSTATE + n]);
    int rowbase = b*LSEQ;
    int gbase = dir*MTOK + rowbase;
    __syncthreads();   // s_dtw/s_dtb ready before first stage

    auto stage = [&](int t0, int bf) {
        // vector loads: xv, B, C, z
        if (tid < 96) {
            int tt = t0 + (tid >> 2);
            if (tt < LSEQ) {
                int mm = dir ? (LSEQ-1 - tt) : tt;
                int gi = gbase + mm;
                int jq = (tid & 3)*4;
                int idx = (tt - t0)*16 + jq;
                *(float4*)&sbuf[bf][1][idx] = *(const float4*)(g_xconv + (size_t)gi*DI + cblk*16 + jq);
                *(float4*)&sbuf[bf][2][idx] = *(const float4*)(g_dbl   + (size_t)gi*DXP + DTRANK + jq);
                *(float4*)&sbuf[bf][3][idx] = *(const float4*)(g_dbl   + (size_t)gi*DXP + DTRANK + DSTATE + jq);
                *(float4*)&sbuf[bf][4][idx] = *(const float4*)(g_xz    + (size_t)(rowbase+mm)*2*DI + DI + cblk*16 + jq);
            }
        }
        // inline dt projection + softplus
        for (int j = tid; j < CT*16; j += 256) {
            int tt = t0 + (j >> 4);
            if (tt < LSEQ) {
                int mm = dir ? (LSEQ-1 - tt) : tt;
                const float* db = g_dbl + (size_t)(gbase + mm)*DXP;
                int ch = j & 15;
                float s = s_dtb[ch];
                #pragma unroll
                for (int r = 0; r < DTRANK; r++) s = fmaf(db[r], s_dtw[ch][r], s);
                sbuf[bf][0][j] = (s > 20.f) ? s : log1pf(__expf(s));
            }
        }
    };

    stage(0, 0);
    __syncthreads();

    float h = 0.f;
    const int nch = (LSEQ + CT - 1)/CT;   // 17
    for (int c = 0; c < nch; c++) {
        int bf = c & 1;
        int tmax = min(CT, LSEQ - c*CT);
        #pragma unroll 4
        for (int k = 0; k < tmax; k++) {
            float dt = sbuf[bf][0][k*16 + dloc];
            float xv = sbuf[bf][1][k*16 + dloc];
            float Bn = sbuf[bf][2][k*16 + n];
            float Cn = sbuf[bf][3][k*16 + n];
            h = fmaf(__expf(dt*A), h, dt*xv*Bn);
            sp[k][dloc][n] = h*Cn;
        }
        __syncthreads();
        if (c + 1 < nch) stage((c+1)*CT, bf ^ 1);
        for (int o = tid; o < tmax*16; o += 256) {
            int k = o >> 4, dd = o & 15;
            float4 p0 = *(const float4*)&sp[k][dd][0];
            float4 p1 = *(const float4*)&sp[k][dd][4];
            float4 p2 = *(const float4*)&sp[k][dd][8];
            float4 p3 = *(const float4*)&sp[k][dd][12];
            float s = ((p0.x+p0.y)+(p0.z+p0.w)) + ((p1.x+p1.y)+(p1.z+p1.w))
                    + ((p2.x+p2.y)+(p2.z+p2.w)) + ((p3.x+p3.y)+(p3.z+p3.w));
            float xvv = sbuf[bf][1][k*16 + dd];
            float z   = sbuf[bf][4][k*16 + dd];
            float y = fmaf(xvv, s_Dk[dd], s);
            int tglob = c*CT + k;
            int mm = dir ? (LSEQ-1 - tglob) : tglob;
            g_y[(size_t)(gbase + mm)*DI + cblk*16 + dd] = y * (z / (1.f + __expf(-z)));
        }
        __syncthreads();
    }
}

// ---------------- final norm + head (cls token only) ----------------
__global__ void k_head(const float* __restrict__ nfw, const float* __restrict__ hw,
                       const float* __restrict__ hb, float* __restrict__ out)
{
    int b = blockIdx.x;
    int tid = threadIdx.x; // 192
    __shared__ float rn[DM];
    __shared__ float red[6];
    int m = b*LSEQ;
    float v = g_residual[m*DM + tid] + g_hidden[m*DM + tid];
    float ss = v*v;
    #pragma unroll
    for (int o = 16; o; o >>= 1) ss += __shfl_xor_sync(~0u, ss, o);
    if ((tid & 31) == 0) red[tid >> 5] = ss;
    __syncthreads();
    float tot = red[0] + red[1] + red[2] + red[3] + red[4] + red[5];
    float rstd = rsqrtf(tot*(1.f/DM) + 1e-5f);
    rn[tid] = v*rstd*nfw[tid];
    __syncthreads();
    if (tid < 22) {
        float s = hb[tid];
        const float* wr = hw + tid*DM;
        #pragma unroll 4
        for (int k = 0; k < DM; k++) s = fmaf(rn[k], wr[k], s);
        out[b*22 + tid] = s;
    }
}

// ---------------- launcher ----------------
extern "C" void kernel_launch(void* const* d_in, const int* in_sizes, int n_in,
                              void* d_out, int out_size)
{
    const float* x         = (const float*)d_in[0];
    const float* pe_w      = (const float*)d_in[1];
    const float* pe_b      = (const float*)d_in[2];
    const float* cls_token = (const float*)d_in[3];
    const float* pos_embed = (const float*)d_in[4];
    const float* norm_w    = (const float*)d_in[5];
    const float* in_proj_w = (const float*)d_in[6];
    const float* cw        = (const float*)d_in[7];
    const float* cb        = (const float*)d_in[8];
    const float* xproj_w   = (const float*)d_in[9];
    const float* dtproj_w  = (const float*)d_in[10];
    const float* dtproj_b  = (const float*)d_in[11];
    const float* A_log     = (const float*)d_in[12];
    const float* A_b_log   = (const float*)d_in[13];
    const float* Dp        = (const float*)d_in[14];
    const float* outproj_w = (const float*)d_in[15];
    const float* norm_f_w  = (const float*)d_in[16];
    const float* head_w    = (const float*)d_in[17];
    const float* head_b    = (const float*)d_in[18];
    float* out = (float*)d_out;

    k_patch<<<dim3(400, NB), 256>>>(x, pe_w, pe_b, cls_token, pos_embed);

    for (int l = 0; l < DEPTH; l++) {
        k_prenorm<<<(MTOK + 7)/8, 256>>>(norm_w + l*DM);
        k_gemm0<<<dim3((MTOK + 127)/128, (2*DI)/64), 256>>>(in_proj_w + (size_t)l*2*DI*DM);
        k_gemm2conv<<<(2*MTOK + 31)/32, 192>>>(xproj_w + (size_t)l*DXP*DI,
                                               cw + l*DI*DCONV, cb + l*DI);
        k_scan<<<dim3(DI/16, NB, 2), 256>>>(A_log + (size_t)l*DI*DSTATE,
                                            A_b_log + (size_t)l*DI*DSTATE,
                                            Dp + l*DI,
                                            dtproj_w + (size_t)l*DI*DTRANK,
                                            dtproj_b + l*DI);
        k_gemm1<<<dim3((MTOK + 63)/64, DM/64), 256>>>(outproj_w + (size_t)l*DM*DI);
    }

    k_head<<<NB, DM>>>(norm_f_w, head_w, head_b, out);
}